// round 15
// baseline (speedup 1.0000x reference)
#include <cuda_runtime.h>
#include <cuda_bf16.h>
#include <math.h>

#define NN 50000
#define EE 400000
#define RR 4
#define HH 2
#define CC 64
#define HCC 128   // H*C
#define RHC 512   // R*H*C
#define LL 2
#define LN_EPS 1e-5f
#define SLOPE 0.2f

#define KEYS (NN * RR)          // 200000; key = r*NN + n (relation-major)
#define SCAN_B 1024
#define SCAN_NBLK ((KEYS + SCAN_B - 1) / SCAN_B)   // 196

// ---------------- scratch (device globals; no allocations allowed) ----------
__device__ float g_feat[NN * RHC];   // RELATION-MAJOR: [r][n][h*64+c]
__device__ float g_agg [NN * RHC];   // node-major: [n][r*128 + h*64 + c]
__device__ float g_es  [NN * 8];     // [r][n][h] as float2 pairs
__device__ float g_ed  [NN * 8];
__device__ float g_h   [NN * 64];    // hidden state between layers
// CSR (built once per call; graph identical across layers)
__device__ int   g_cnt[KEYS];
__device__ int   g_off[KEYS];
__device__ int   g_cur[KEYS];
__device__ int   g_bsum[SCAN_NBLK];
__device__ int   g_src[2 * EE];
// pre-split weights in MMA-fragment uint4 layout {bh0,bh1,bl0,bl1}
__device__ uint4 g_wgf[LL * RR * 128 * 16];   // GAT W: [(l,r)][n(128)][ks(4)*q(4)]
__device__ uint4 g_w1f[LL * 9 * 64 * 16];     // MLP W1: [(l,ch)][n(64)][16]
__device__ uint4 g_w2f[LL * 64 * 16];         // MLP W2: [l][n(64)][16]

__device__ __forceinline__ float lrelu(float x) { return x > 0.f ? x : SLOPE * x; }

__device__ __forceinline__ void split2(float2 v, unsigned& hi, unsigned& lo)
{
    __nv_bfloat162 h = __floats2bfloat162_rn(v.x, v.y);
    float2 hf = __bfloat1622float2(h);
    __nv_bfloat162 l = __floats2bfloat162_rn(v.x - hf.x, v.y - hf.y);
    hi = *(unsigned*)&h;
    lo = *(unsigned*)&l;
}

__device__ __forceinline__ void mma16816(float* c, const unsigned* a,
                                         unsigned b0, unsigned b1)
{
    asm volatile(
        "mma.sync.aligned.m16n8k16.row.col.f32.bf16.bf16.f32 "
        "{%0,%1,%2,%3}, {%4,%5,%6,%7}, {%8,%9}, {%0,%1,%2,%3};"
        : "+f"(c[0]), "+f"(c[1]), "+f"(c[2]), "+f"(c[3])
        : "r"(a[0]), "r"(a[1]), "r"(a[2]), "r"(a[3]), "r"(b0), "r"(b1));
}

__device__ __forceinline__ void mma_pack(float* c, const unsigned* ahi,
                                         const unsigned* alo, uint4 f)
{
    mma16816(c, ahi, f.x, f.y);   // hi*hi
    mma16816(c, ahi, f.z, f.w);   // hi*lo
    mma16816(c, alo, f.x, f.y);   // lo*hi
}

__device__ __forceinline__ void cp_async16(void* smem, const void* gmem)
{
    unsigned saddr = (unsigned)__cvta_generic_to_shared(smem);
    asm volatile("cp.async.cg.shared.global [%0], [%1], 16;"
                 :: "r"(saddr), "l"(gmem));
}
__device__ __forceinline__ void cp_commit()
{
    asm volatile("cp.async.commit_group;");
}
__device__ __forceinline__ void cp_wait0()
{
    asm volatile("cp.async.wait_group 0;");
}

// ================= k_init: zero counts + pre-split all weights ===============
__global__ void k_init(const float* __restrict__ gW,
                       const float* __restrict__ W1, const float* __restrict__ W2)
{
    int i = blockIdx.x * blockDim.x + threadIdx.x;
    if (i < KEYS) g_cnt[i] = 0;

    if (i < LL * RR * 128 * 16) {          // GAT weight split
        int q  = i & 3;
        int ks = (i >> 2) & 3;
        int n  = (i >> 4) & 127;
        int lr = i >> 11;
        const float* Wb = gW + lr * 64 * 128;    // [k][n]
        int k0 = ks * 16 + q * 2;
        unsigned h0, l0, h1, l1;
        split2(make_float2(Wb[k0 * 128 + n],       Wb[(k0 + 1) * 128 + n]), h0, l0);
        split2(make_float2(Wb[(k0 + 8) * 128 + n], Wb[(k0 + 9) * 128 + n]), h1, l1);
        g_wgf[(lr * 128 + n) * 16 + ks * 4 + q] = make_uint4(h0, h1, l0, l1);
    }
    if (i < LL * 9 * 64 * 16) {            // MLP W1 split
        int q  = i & 3;
        int ks = (i >> 2) & 3;
        int n  = (i >> 4) & 63;
        int ch = (i >> 10) % 9;
        int l  = i / (9 * 1024);
        const float* Wb = W1 + l * 576 * 64;
        int k0 = ch * 64 + ks * 16 + q * 2;
        unsigned h0, l0, h1, l1;
        split2(make_float2(Wb[k0 * 64 + n],       Wb[(k0 + 1) * 64 + n]), h0, l0);
        split2(make_float2(Wb[(k0 + 8) * 64 + n], Wb[(k0 + 9) * 64 + n]), h1, l1);
        g_w1f[((l * 9 + ch) * 64 + n) * 16 + ks * 4 + q] = make_uint4(h0, h1, l0, l1);
    }
    if (i < LL * 64 * 16) {                // MLP W2 split
        int q  = i & 3;
        int ks = (i >> 2) & 3;
        int n  = (i >> 4) & 63;
        int l  = i >> 10;
        const float* Wb = W2 + l * 64 * 64;
        int k0 = ks * 16 + q * 2;
        unsigned h0, l0, h1, l1;
        split2(make_float2(Wb[k0 * 64 + n],       Wb[(k0 + 1) * 64 + n]), h0, l0);
        split2(make_float2(Wb[(k0 + 8) * 64 + n], Wb[(k0 + 9) * 64 + n]), h1, l1);
        g_w2f[(l * 64 + n) * 16 + ks * 4 + q] = make_uint4(h0, h1, l0, l1);
    }
}

// ================= CSR build (relation-major keys) ===========================
__global__ void k_count(const int* __restrict__ ei, const float* __restrict__ ew)
{
    int e = blockIdx.x * blockDim.x + threadIdx.x;
    if (e >= EE) return;
    int s = ei[e], d = ei[EE + e];
    float w = ew[e];
    if (w == 0.f) return;
    int r0 = (w > 0.f) ? 0 : 2;
    atomicAdd(&g_cnt[r0 * NN + d], 1);
    atomicAdd(&g_cnt[(r0 + 1) * NN + s], 1);
}

__global__ void k_scan1()
{
    __shared__ int sh[SCAN_B];
    int tid = threadIdx.x;
    int i = blockIdx.x * SCAN_B + tid;
    int v = (i < KEYS) ? g_cnt[i] : 0;
    sh[tid] = v;
    __syncthreads();
    #pragma unroll
    for (int off = 1; off < SCAN_B; off <<= 1) {
        int t = (tid >= off) ? sh[tid - off] : 0;
        __syncthreads();
        sh[tid] += t;
        __syncthreads();
    }
    if (i < KEYS) g_off[i] = sh[tid] - v;
    if (tid == SCAN_B - 1) g_bsum[blockIdx.x] = sh[tid];
}

__global__ void k_scan2()
{
    __shared__ int sh[256];
    int t = threadIdx.x;
    int v = (t < SCAN_NBLK) ? g_bsum[t] : 0;
    sh[t] = v;
    __syncthreads();
    #pragma unroll
    for (int off = 1; off < 256; off <<= 1) {
        int x = (t >= off) ? sh[t - off] : 0;
        __syncthreads();
        sh[t] += x;
        __syncthreads();
    }
    if (t < SCAN_NBLK) g_bsum[t] = sh[t] - v;
}

__global__ void k_scan3()
{
    int i = blockIdx.x * blockDim.x + threadIdx.x;
    if (i >= KEYS) return;
    int o = g_off[i] + g_bsum[i >> 10];
    g_off[i] = o;
    g_cur[i] = o;
}

__global__ void k_fill(const int* __restrict__ ei, const float* __restrict__ ew)
{
    int e = blockIdx.x * blockDim.x + threadIdx.x;
    if (e >= EE) return;
    int s = ei[e], d = ei[EE + e];
    float w = ew[e];
    if (w == 0.f) return;
    int r0 = (w > 0.f) ? 0 : 2;
    int p1 = atomicAdd(&g_cur[r0 * NN + d], 1);
    g_src[p1] = s;
    int p2 = atomicAdd(&g_cur[(r0 + 1) * NN + s], 1);
    g_src[p2] = d;
}

// ================= feat GEMM: relation loop, A cached in registers ===========
// Block = 128 nodes x ALL 4 relations. A split once (32 regs); W tiles double-
// buffered via cp.async so the r+1 copy overlaps the r compute.
__global__ __launch_bounds__(256, 2) void k_feat_mma(
    const float* __restrict__ hin, int l,
    const float* __restrict__ asrc, const float* __restrict__ adst)
{
    __shared__ uint4 sW[2][128 * 20];      // 2 x 40KB
    __shared__ float4 s_asad[4][64];       // {as[c],as[c+1],ad[c],ad[c+1]} per r

    const int tid = threadIdx.x;
    const int nb  = blockIdx.x * 128;
    const int w = tid >> 5, ln = tid & 31;
    const int g = ln >> 2, q = ln & 3;
    const int row0 = nb + w * 16 + g;
    const int ra = min(row0, NN - 1);
    const int rb = min(row0 + 8, NN - 1);
    const bool ok0 = row0 < NN, ok1 = (row0 + 8) < NN;

    // issue W copy for relation 0
    {
        const uint4* wg = g_wgf + (size_t)(l * RR + 0) * 128 * 16;
        #pragma unroll
        for (int i = tid; i < 2048; i += 256)
            cp_async16(&sW[0][(i >> 4) * 20 + (i & 15)], &wg[i]);
        cp_commit();
    }
    // attention vectors for all relations (256 entries, one per thread)
    {
        int rr = tid >> 6, j = tid & 63;
        float2 a = ((const float2*)(asrc + rr * 128))[j];
        float2 d = ((const float2*)(adst + rr * 128))[j];
        s_asad[rr][j] = make_float4(a.x, a.y, d.x, d.y);
    }

    // split A once (overlaps with the cp.async of W0)
    unsigned ahi[4][4], alo[4][4];
    #pragma unroll
    for (int ks = 0; ks < 4; ks++) {
        int c0 = ks * 16 + q * 2;
        float2 x00 = *(const float2*)(hin + ra * 64 + c0);
        float2 x10 = *(const float2*)(hin + rb * 64 + c0);
        float2 x01 = *(const float2*)(hin + ra * 64 + c0 + 8);
        float2 x11 = *(const float2*)(hin + rb * 64 + c0 + 8);
        split2(x00, ahi[ks][0], alo[ks][0]);
        split2(x10, ahi[ks][1], alo[ks][1]);
        split2(x01, ahi[ks][2], alo[ks][2]);
        split2(x11, ahi[ks][3], alo[ks][3]);
    }

    const unsigned FULL = 0xffffffffu;
    float2* out2 = (float2*)g_feat;
    float2* es2 = (float2*)g_es;
    float2* ed2 = (float2*)g_ed;

    for (int r = 0; r < RR; r++) {
        cp_wait0();
        __syncthreads();
        if (r + 1 < RR) {                   // prefetch next relation's W
            const uint4* wg = g_wgf + (size_t)(l * RR + r + 1) * 128 * 16;
            #pragma unroll
            for (int i = tid; i < 2048; i += 256)
                cp_async16(&sW[(r + 1) & 1][(i >> 4) * 20 + (i & 15)], &wg[i]);
            cp_commit();
        }
        const uint4* W = sW[r & 1];

        float c[16][4];
        #pragma unroll
        for (int t = 0; t < 16; t++) {
            c[t][0] = 0.f; c[t][1] = 0.f; c[t][2] = 0.f; c[t][3] = 0.f;
        }
        #pragma unroll
        for (int ks = 0; ks < 4; ks++) {
            #pragma unroll
            for (int t = 0; t < 16; t++) {
                uint4 f = W[(t * 8 + g) * 20 + ks * 4 + q];
                mma_pack(c[t], ahi[ks], alo[ks], f);
            }
        }

        // stores (relation-major feat) + fused scores
        float esA[2] = {0.f, 0.f}, edA[2] = {0.f, 0.f};
        float esB[2] = {0.f, 0.f}, edB[2] = {0.f, 0.f};
        #pragma unroll
        for (int t = 0; t < 16; t++) {
            int colw = t * 4 + q;
            if (ok0) out2[(r * NN + row0) * 64 + colw] = make_float2(c[t][0], c[t][1]);
            if (ok1) out2[(r * NN + row0 + 8) * 64 + colw] = make_float2(c[t][2], c[t][3]);
            float4 aa = s_asad[r][t * 4 + q];
            int hd = t >> 3;                 // cols 0-63 head0, 64-127 head1
            esA[hd] += c[t][0] * aa.x + c[t][1] * aa.y;
            edA[hd] += c[t][0] * aa.z + c[t][1] * aa.w;
            esB[hd] += c[t][2] * aa.x + c[t][3] * aa.y;
            edB[hd] += c[t][2] * aa.z + c[t][3] * aa.w;
        }
        #pragma unroll
        for (int o = 1; o <= 2; o <<= 1) {
            esA[0] += __shfl_xor_sync(FULL, esA[0], o);
            esA[1] += __shfl_xor_sync(FULL, esA[1], o);
            esB[0] += __shfl_xor_sync(FULL, esB[0], o);
            esB[1] += __shfl_xor_sync(FULL, esB[1], o);
            edA[0] += __shfl_xor_sync(FULL, edA[0], o);
            edA[1] += __shfl_xor_sync(FULL, edA[1], o);
            edB[0] += __shfl_xor_sync(FULL, edB[0], o);
            edB[1] += __shfl_xor_sync(FULL, edB[1], o);
        }
        if (q == 0) {
            if (ok0) {
                es2[r * NN + row0] = make_float2(esA[0], esA[1]);
                ed2[r * NN + row0] = make_float2(edA[0], edA[1]);
            }
            if (ok1) {
                es2[r * NN + row0 + 8] = make_float2(esB[0], esB[1]);
                ed2[r * NN + row0 + 8] = make_float2(edB[0], edB[1]);
            }
        }
        __syncthreads();   // all reads of sW[r&1] done before r+2 overwrites it
    }
}

// ---------------- fused GAT: single-pass online softmax + aggregation -------
// key = r*NN + n; relation-ordered blocks keep the gather slice L2-resident.
__global__ void k_gat(const float* __restrict__ bias)
{
    const unsigned FULL = 0xffffffffu;
    int key = blockIdx.x * 8 + (threadIdx.x >> 5);
    if (key >= KEYS) return;
    int lane = threadIdx.x & 31;
    int r = key / NN, n = key - r * NN;

    int beg = g_off[key];
    int num = g_cnt[key];

    const float2* es2 = (const float2*)g_es;
    float2 edv = ((const float2*)g_ed)[key];
    float2 esn = es2[key];
    float self0 = lrelu(esn.x + edv.x);
    float self1 = lrelu(esn.y + edv.y);

    float m0 = self0, m1 = self1;
    float den0 = 0.f, den1 = 0.f;
    float4 acc = make_float4(0.f, 0.f, 0.f, 0.f);
    const float4* feat4 = (const float4*)g_feat + (size_t)r * NN * 32;

    for (int base = 0; base < num; base += 32) {
        int cnt = min(32, num - base);
        int sj = 0;
        float ex = 0.f, ey = 0.f;
        if (lane < cnt) {
            sj = g_src[beg + base + lane];
            float2 e2 = es2[r * NN + sj];
            ex = e2.x; ey = e2.y;
        }
        // prefetch edge 0's feat row
        int s0 = __shfl_sync(FULL, sj, 0);
        float4 f = feat4[s0 * 32 + lane];
        for (int j = 0; j < cnt; j++) {
            float jx = __shfl_sync(FULL, ex, j);
            float jy = __shfl_sync(FULL, ey, j);
            float4 fc = f;
            if (j + 1 < cnt) {               // prefetch next edge's row
                int sn = __shfl_sync(FULL, sj, j + 1);
                f = feat4[sn * 32 + lane];
            }
            float e0 = lrelu(jx + edv.x);
            float e1 = lrelu(jy + edv.y);
            if (e0 > m0 || e1 > m1) {        // warp-uniform rescale path
                float nm0 = fmaxf(m0, e0), nm1 = fmaxf(m1, e1);
                float c0 = __expf(m0 - nm0), c1 = __expf(m1 - nm1);
                float p0 = __expf(e0 - nm0), p1 = __expf(e1 - nm1);
                den0 = den0 * c0 + p0;
                den1 = den1 * c1 + p1;
                m0 = nm0; m1 = nm1;
                float cl = (lane < 16) ? c0 : c1;
                float pl = (lane < 16) ? p0 : p1;
                acc.x = acc.x * cl + pl * fc.x;
                acc.y = acc.y * cl + pl * fc.y;
                acc.z = acc.z * cl + pl * fc.z;
                acc.w = acc.w * cl + pl * fc.w;
            } else {
                float p0 = __expf(e0 - m0);
                float p1 = __expf(e1 - m1);
                den0 += p0; den1 += p1;
                float pl = (lane < 16) ? p0 : p1;
                acc.x += pl * fc.x; acc.y += pl * fc.y;
                acc.z += pl * fc.z; acc.w += pl * fc.w;
            }
        }
    }
    // self loop (self <= m always)
    {
        float p0 = __expf(self0 - m0);
        float p1 = __expf(self1 - m1);
        den0 += p0; den1 += p1;
        float pl = (lane < 16) ? p0 : p1;
        float4 f = feat4[n * 32 + lane];
        acc.x += pl * f.x; acc.y += pl * f.y;
        acc.z += pl * f.z; acc.w += pl * f.w;
    }

    float inv = 1.f / ((lane < 16) ? den0 : den1);
    float4 b = ((const float4*)bias)[r * 32 + lane];
    ((float4*)g_agg)[n * 128 + r * 32 + lane] =
        make_float4(acc.x * inv + b.x, acc.y * inv + b.y,
                    acc.z * inv + b.z, acc.w * inv + b.w);
}

// ================= MLP via bf16-split MMA + fused residual/LN ================
__global__ __launch_bounds__(256, 3) void k_mlp_mma(
    const float* __restrict__ hin, int l,
    const float* __restrict__ b1, const float* __restrict__ b2,
    const float* __restrict__ lng, const float* __restrict__ lnb,
    float* __restrict__ hout)
{
    __shared__ uint4 sW[64 * 20];
    __shared__ float2 s_b1[32];        // {b1[c], b1[c+1]}
    __shared__ float4 s_bg[32];        // {b2[c], b2[c+1], lng[c], lng[c+1]}
    __shared__ float2 s_lb[32];        // {lnb[c], lnb[c+1]}

    const int tid = threadIdx.x;
    const int w = tid >> 5, ln = tid & 31;
    const int g = ln >> 2, q = ln & 3;
    const int nb = blockIdx.x * 128;
    const int row0 = nb + w * 16 + g;
    const int ra = min(row0, NN - 1);
    const int rb = min(row0 + 8, NN - 1);

    if (tid < 32) {
        s_b1[tid] = ((const float2*)b1)[tid];
        float2 bb = ((const float2*)b2)[tid];
        float2 gg = ((const float2*)lng)[tid];
        s_bg[tid] = make_float4(bb.x, bb.y, gg.x, gg.y);
        s_lb[tid] = ((const float2*)lnb)[tid];
    }

    float c1[8][4];
    #pragma unroll
    for (int t = 0; t < 8; t++) {
        c1[t][0] = 0.f; c1[t][1] = 0.f; c1[t][2] = 0.f; c1[t][3] = 0.f;
    }

    const uint4* w1f = g_w1f + l * 9 * 1024;

    for (int ch = 0; ch < 9; ch++) {
        __syncthreads();
        #pragma unroll
        for (int i = tid; i < 1024; i += 256) {
            sW[(i >> 4) * 20 + (i & 15)] = w1f[ch * 1024 + i];
        }
        __syncthreads();

        #pragma unroll
        for (int ks = 0; ks < 4; ks++) {
            float2 x00, x10, x01, x11;
            if (ch == 0) {
                int c0 = ks * 16 + q * 2;
                x00 = *(const float2*)(hin + ra * 64 + c0);
                x10 = *(const float2*)(hin + rb * 64 + c0);
                x01 = *(const float2*)(hin + ra * 64 + c0 + 8);
                x11 = *(const float2*)(hin + rb * 64 + c0 + 8);
            } else {
                int c0 = (ch - 1) * 64 + ks * 16 + q * 2;
                x00 = *(const float2*)(g_agg + ra * 512 + c0);
                x10 = *(const float2*)(g_agg + rb * 512 + c0);
                x01 = *(const float2*)(g_agg + ra * 512 + c0 + 8);
                x11 = *(const float2*)(g_agg + rb * 512 + c0 + 8);
            }
            unsigned ahi[4], alo[4];
            split2(x00, ahi[0], alo[0]);
            split2(x10, ahi[1], alo[1]);
            split2(x01, ahi[2], alo[2]);
            split2(x11, ahi[3], alo[3]);

            #pragma unroll
            for (int t = 0; t < 8; t++) {
                uint4 f = sW[(t * 8 + g) * 20 + ks * 4 + q];
                mma_pack(c1[t], ahi, alo, f);
            }
        }
    }

    // ---- tanh + bias -> A fragments for GEMM2 ----
    unsigned ahi2[4][4], alo2[4][4];
    #pragma unroll
    for (int t = 0; t < 8; t++) {
        float2 bj = s_b1[t * 4 + q];
        float z0 = tanhf(c1[t][0] + bj.x);
        float z1 = tanhf(c1[t][1] + bj.y);
        float z2 = tanhf(c1[t][2] + bj.x);
        float z3 = tanhf(c1[t][3] + bj.y);
        int kt = t >> 1;
        int o = (t & 1) ? 2 : 0;
        split2(make_float2(z0, z1), ahi2[kt][o + 0], alo2[kt][o + 0]);
        split2(make_float2(z2, z3), ahi2[kt][o + 1], alo2[kt][o + 1]);
    }

    __syncthreads();
    #pragma unroll
    for (int i = tid; i < 1024; i += 256) {
        sW[(i >> 4) * 20 + (i & 15)] = g_w2f[l * 1024 + i];
    }
    __syncthreads();

    float c2[8][4];
    #pragma unroll
    for (int t = 0; t < 8; t++) {
        c2[t][0] = 0.f; c2[t][1] = 0.f; c2[t][2] = 0.f; c2[t][3] = 0.f;
    }
    #pragma unroll
    for (int kt = 0; kt < 4; kt++) {
        #pragma unroll
        for (int t = 0; t < 8; t++) {
            uint4 f = sW[(t * 8 + g) * 20 + kt * 4 + q];
            mma_pack(c2[t], ahi2[kt], alo2[kt], f);
        }
    }

    // ---- +b2 +residual (in place), LayerNorm sums ----
    float sA = 0.f, qA = 0.f, sB = 0.f, qB = 0.f;
    #pragma unroll
    for (int t = 0; t < 8; t++) {
        int col0 = t * 8 + q * 2;
        float4 bg = s_bg[t * 4 + q];
        float2 r0 = *(const float2*)(hin + ra * 64 + col0);
        float2 r1 = *(const float2*)(hin + rb * 64 + col0);
        c2[t][0] += bg.x + r0.x;
        c2[t][1] += bg.y + r0.y;
        c2[t][2] += bg.x + r1.x;
        c2[t][3] += bg.y + r1.y;
        sA += c2[t][0] + c2[t][1];
        qA += c2[t][0] * c2[t][0] + c2[t][1] * c2[t][1];
        sB += c2[t][2] + c2[t][3];
        qB += c2[t][2] * c2[t][2] + c2[t][3] * c2[t][3];
    }
    const unsigned FULL = 0xffffffffu;
    #pragma unroll
    for (int o = 1; o <= 2; o <<= 1) {
        sA += __shfl_xor_sync(FULL, sA, o);
        qA += __shfl_xor_sync(FULL, qA, o);
        sB += __shfl_xor_sync(FULL, sB, o);
        qB += __shfl_xor_sync(FULL, qB, o);
    }
    float muA = sA * (1.f / 64.f);
    float rsA = rsqrtf(qA * (1.f / 64.f) - muA * muA + LN_EPS);
    float muB = sB * (1.f / 64.f);
    float rsB = rsqrtf(qB * (1.f / 64.f) - muB * muB + LN_EPS);

    const bool ok0 = row0 < NN, ok1 = (row0 + 8) < NN;
    #pragma unroll
    for (int t = 0; t < 8; t++) {
        int col0 = t * 8 + q * 2;
        float4 bg = s_bg[t * 4 + q];
        float2 ob = s_lb[t * 4 + q];
        if (ok0)
            *(float2*)(hout + row0 * 64 + col0) =
                make_float2((c2[t][0] - muA) * rsA * bg.z + ob.x,
                            (c2[t][1] - muA) * rsA * bg.w + ob.y);
        if (ok1)
            *(float2*)(hout + (row0 + 8) * 64 + col0) =
                make_float2((c2[t][2] - muB) * rsB * bg.z + ob.x,
                            (c2[t][3] - muB) * rsB * bg.w + ob.y);
    }
}

// ---------------- launch -----------------------------------------------------
extern "C" void kernel_launch(void* const* d_in, const int* in_sizes, int n_in,
                              void* d_out, int out_size)
{
    const float* x   = (const float*)d_in[0];
    const int*   ei  = (const int*)  d_in[1];
    const float* ew  = (const float*)d_in[2];
    const float* gW  = (const float*)d_in[3];
    const float* gas = (const float*)d_in[4];
    const float* gad = (const float*)d_in[5];
    const float* gb  = (const float*)d_in[6];
    const float* W1  = (const float*)d_in[7];
    const float* b1  = (const float*)d_in[8];
    const float* W2  = (const float*)d_in[9];
    const float* b2  = (const float*)d_in[10];
    const float* lng = (const float*)d_in[11];
    const float* lnb = (const float*)d_in[12];
    float* out = (float*)d_out;

    float* hptr = nullptr;
    cudaGetSymbolAddress((void**)&hptr, g_h);

    const int EB  = (EE + 255) / 256;
    const int KB  = (KEYS + 255) / 256;
    const int FT  = (NN + 127) / 128;       // 391 tiles of 128 nodes

    // k_feat_mma at launch index 3 (ncu capture slot)
    k_init <<<KB, 256>>>(gW, W1, W2);
    k_count<<<EB, 256>>>(ei, ew);
    k_scan1<<<SCAN_NBLK, SCAN_B>>>();
    k_feat_mma<<<FT, 256>>>(x, 0, gas, gad);          // layer 0, all relations
    k_scan2<<<1, 256>>>();
    k_scan3<<<KB, 256>>>();
    k_fill <<<EB, 256>>>(ei, ew);

    // layer 0 tail
    k_gat<<<KEYS / 8, 256>>>(gb);
    k_mlp_mma<<<FT, 256>>>(x, 0, b1, b2, lng, lnb, hptr);

    // layer 1
    k_feat_mma<<<FT, 256>>>(hptr, 1, gas + RR * HH * CC, gad + RR * HH * CC);
    k_gat<<<KEYS / 8, 256>>>(gb + RR * HCC);
    k_mlp_mma<<<FT, 256>>>(hptr, 1, b1 + 64, b2 + 64,
                           lng + 64, lnb + 64, out);
}